// round 16
// baseline (speedup 1.0000x reference)
#include <cuda_runtime.h>
#include <cuda_bf16.h>
#include <cuda_fp16.h>
#include <math.h>
#include <stdint.h>

// Problem constants
#define TX 64
#define BB 64
#define TY 32
#define EE 256
#define HH 512
#define H3 1536
#define KY 32000
#define CTXD 1024      // 2H
#define RNNIN 1280     // E + 2H
#define NTILE (KY / 128)   // 250 vocab tiles (M=128)

// ---------------- device scratch ----------------
__device__ float g_gi_f[TX * BB * H3];
__device__ float g_gi_b[TX * BB * H3];
__device__ float g_henc[2][2][BB * HH];
__device__ float g_enc[TX * BB * CTXD];
__device__ float g_P[TX * BB * HH];
__device__ float g_hd[2][BB * HH];
__device__ float g_q[BB * HH];
__device__ float g_lin[BB * H3];     // fp32 [h2, context] for exact-argmax rescue
__device__ float g_rnnin[BB * RNNIN];
__device__ int   g_tok[BB];
__device__ float g_lse[TY * BB];

__device__ __half g_wh[(size_t)KY * H3];   // fp16(W_lsm)
__device__ __half g_ah[BB * H3];           // fp16 of [h2, context]

// per-tile softmax partials (top-2 + sum)
__device__ float g_pm[NTILE][BB];
__device__ int   g_pa[NTILE][BB];
__device__ float g_pm2[NTILE][BB];
__device__ int   g_pa2[NTILE][BB];
__device__ float g_ps[NTILE][BB];

__device__ volatile unsigned g_bar_gen[3];
__device__ unsigned g_bar_cnt[3];

__device__ __forceinline__ float sigm(float x) { return 1.0f / (1.0f + expf(-x)); }

// ---------------- init ----------------
__global__ void init_kernel() {
    int i = blockIdx.x * blockDim.x + threadIdx.x;
    if (i < BB * HH) {
        g_henc[0][0][i] = 0.f;
        g_henc[1][0][i] = 0.f;
    }
    if (i < BB) g_tok[i] = 1;
    if (i < 3) { g_bar_gen[i] = 0; g_bar_cnt[i] = 0; }
}

// ---------------- W_lsm -> fp16 ----------------
__global__ __launch_bounds__(256) void convw_kernel(const float* __restrict__ W) {
    size_t i = (size_t)blockIdx.x * blockDim.x + threadIdx.x;
    const float4* W4 = (const float4*)W;
    float4 v = W4[i];
    __half2* H2 = reinterpret_cast<__half2*>(g_wh);
    H2[2 * i]     = __halves2half2(__float2half_rn(v.x), __float2half_rn(v.y));
    H2[2 * i + 1] = __halves2half2(__float2half_rn(v.z), __float2half_rn(v.w));
}

// ---------------- mma.sync fp16 helper ----------------
__device__ __forceinline__ void mma16816h(float* d, const uint32_t* a, uint32_t b0, uint32_t b1)
{
    asm volatile(
        "mma.sync.aligned.m16n8k16.row.col.f32.f16.f16.f32 "
        "{%0,%1,%2,%3}, {%4,%5,%6,%7}, {%8,%9}, {%0,%1,%2,%3};"
        : "+f"(d[0]), "+f"(d[1]), "+f"(d[2]), "+f"(d[3])
        : "r"(a[0]), "r"(a[1]), "r"(a[2]), "r"(a[3]), "r"(b0), "r"(b1));
}

__device__ __forceinline__ void merge2(float& v1, int& i1, float& v2, int& i2, float v, int i)
{
    if (v > v1 || (v == v1 && i < i1)) { v2 = v1; i2 = i1; v1 = v; i1 = i; }
    else if (v > v2 || (v == v2 && i < i2)) { v2 = v; i2 = i; }
}

// ---------------- software grid barrier ----------------
__device__ __forceinline__ void grid_barrier(int slot, int nm1, int tid)
{
    __threadfence();
    __syncthreads();
    if (tid == 0) {
        unsigned gen = g_bar_gen[slot];
        unsigned t = atomicAdd(&g_bar_cnt[slot], 1u);
        if (t == (unsigned)nm1) {
            g_bar_cnt[slot] = 0u;
            __threadfence();
            g_bar_gen[slot] = gen + 1u;
        } else {
            while (g_bar_gen[slot] == gen) __nanosleep(40);
        }
    }
    __syncthreads();
}

// ---------------- logits GEMM: M=128 tiles, 250 CTAs, 2 CTAs/SM, 4-stage ----------------
// Also normalizes step s-1's output tile (lse ready from step_kernel phase0),
// overlapped with the pipeline fill.
#define LG_KC 64
#define LG_ROWB 144
#define LG_W_BYTES (128 * LG_ROWB)                 // 18432
#define LG_A_BYTES (64 * LG_ROWB)                  // 9216
#define LG_STAGE (LG_W_BYTES + LG_A_BYTES)         // 27648
#define LG_NSTAGE 4
#define LG_SMEM_TOTAL (LG_NSTAGE * LG_STAGE)       // 110592

__global__ __launch_bounds__(256, 2) void logits_mma_kernel(
    const float* __restrict__ b_lsm, float* __restrict__ out, int step)
{
    extern __shared__ char smem[];
    int tid = threadIdx.x;
    int wid = tid >> 5, lane = tid & 31;
    int vb = blockIdx.x * 128;

    auto load_chunk = [&](int kc, int buf) {
        char* base = smem + buf * LG_STAGE;
        {
            char* dst = base;
            const __half* sh = g_wh + (size_t)vb * H3 + kc * LG_KC;
#pragma unroll
            for (int it = 0; it < 4; it++) {
                int idx = tid + it * 256;
                int r = idx >> 3, c = idx & 7;
                size_t gofs = (size_t)r * H3 + c * 8;
                uint32_t so = (uint32_t)(r * LG_ROWB + c * 16);
                uint32_t d1 = (uint32_t)__cvta_generic_to_shared(dst + so);
                asm volatile("cp.async.cg.shared.global [%0], [%1], 16;" :: "r"(d1), "l"(sh + gofs));
            }
        }
        {
            char* dst = base + LG_W_BYTES;
            const __half* sa = g_ah + kc * LG_KC;
#pragma unroll
            for (int it = 0; it < 2; it++) {
                int idx = tid + it * 256;
                int r = idx >> 3, c = idx & 7;
                size_t gofs = (size_t)r * H3 + c * 8;
                uint32_t so = (uint32_t)(r * LG_ROWB + c * 16);
                uint32_t d1 = (uint32_t)__cvta_generic_to_shared(dst + so);
                asm volatile("cp.async.cg.shared.global [%0], [%1], 16;" :: "r"(d1), "l"(sa + gofs));
            }
        }
        asm volatile("cp.async.commit_group;" ::: "memory");
    };

    float acc[8][4];
#pragma unroll
    for (int nt = 0; nt < 8; nt++)
#pragma unroll
        for (int i = 0; i < 4; i++) acc[nt][i] = 0.f;

    int m0 = wid * 16;
    int krow = lane >> 2;
    int kcol4 = (lane & 3) * 4;

    const int NC = H3 / LG_KC;   // 24
    load_chunk(0, 0);
    load_chunk(1, 1);
    load_chunk(2, 2);
    load_chunk(3, 3);

    // ---- overlapped with pipeline fill: normalize this tile of step s-1 ----
    if (step > 0) {
        const float* lsep = g_lse + (size_t)(step - 1) * BB;
        float* oprev = out + (size_t)(step - 1) * BB * KY + vb;
        int col = tid & 127;
        int rofs = tid >> 7;
#pragma unroll 8
        for (int it = 0; it < 32; it++) {
            int r = it * 2 + rofs;
            oprev[(size_t)r * KY + col] -= lsep[r];
        }
    }

    int buf = 0;
    for (int c = 0; c < NC; c++) {
        int ahead = NC - 1 - c;
        if (ahead >= 3) {
            asm volatile("cp.async.wait_group 3;" ::: "memory");
        } else if (ahead == 2) {
            asm volatile("cp.async.wait_group 2;" ::: "memory");
        } else if (ahead == 1) {
            asm volatile("cp.async.wait_group 1;" ::: "memory");
        } else {
            asm volatile("cp.async.wait_group 0;" ::: "memory");
        }
        __syncthreads();

        char* base = smem + buf * LG_STAGE;
        const char* wh = base;
        const char* ab = base + LG_W_BYTES;

#pragma unroll
        for (int kt = 0; kt < 4; kt++) {
            int kb = kt * 32 + kcol4;
            uint32_t wf[4];
            int ro = (m0 + krow) * LG_ROWB + kb;
            wf[0] = *(const uint32_t*)(wh + ro);
            wf[1] = *(const uint32_t*)(wh + ro + 8 * LG_ROWB);
            wf[2] = *(const uint32_t*)(wh + ro + 16);
            wf[3] = *(const uint32_t*)(wh + ro + 8 * LG_ROWB + 16);
#pragma unroll
            for (int nt = 0; nt < 8; nt++) {
                int rb = (nt * 8 + krow) * LG_ROWB + kb;
                uint32_t b0 = *(const uint32_t*)(ab + rb);
                uint32_t b1 = *(const uint32_t*)(ab + rb + 16);
                mma16816h(acc[nt], wf, b0, b1);
            }
        }
        __syncthreads();
        if (c + 4 < NC) load_chunk(c + 4, buf);
        buf = (buf + 1 == LG_NSTAGE) ? 0 : buf + 1;
    }

    // ---- epilogue: bias + transpose-stage + coalesced store ----
    float* st = (float*)smem;                       // [64][132]
#pragma unroll
    for (int h = 0; h < 2; h++) {
        int vloc = m0 + krow + h * 8;
        float bias = b_lsm[vb + vloc];
#pragma unroll
        for (int nt = 0; nt < 8; nt++) {
            int b0 = nt * 8 + (lane & 3) * 2;
            float x0 = acc[nt][h * 2 + 0] + bias;
            float x1 = acc[nt][h * 2 + 1] + bias;
            acc[nt][h * 2 + 0] = x0;
            acc[nt][h * 2 + 1] = x1;
            st[b0 * 132 + vloc]       = x0;
            st[(b0 + 1) * 132 + vloc] = x1;
        }
    }
    __syncthreads();
    {
        float* obase = out + (size_t)step * BB * KY + vb;
        int col = tid & 127;
        int rofs = tid >> 7;
#pragma unroll 8
        for (int it = 0; it < 32; it++) {
            int r = it * 2 + rofs;
            obase[(size_t)r * KY + col] = st[r * 132 + col];
        }
    }

    // ---- per-tile top-2 + sum partials ----
    float* sv1 = (float*)(smem + 33792);
    int*   si1 = (int*)(smem + 35840);
    float* sv2 = (float*)(smem + 37888);
    int*   si2 = (int*)(smem + 39936);
    float* tmx = (float*)(smem + 41984);

    int vbase = vb + m0 + krow;
#pragma unroll
    for (int nt = 0; nt < 8; nt++) {
#pragma unroll
        for (int c = 0; c < 2; c++) {
            int bcol = nt * 8 + (lane & 3) * 2 + c;
            float v1 = acc[nt][c];     int i1 = vbase;
            float v2 = -1e30f;         int i2 = 0x7fffffff;
            merge2(v1, i1, v2, i2, acc[nt][2 + c], vbase + 8);
#pragma unroll
            for (int o = 4; o <= 16; o <<= 1) {
                float ov1 = __shfl_xor_sync(0xffffffffu, v1, o);
                int   oi1 = __shfl_xor_sync(0xffffffffu, i1, o);
                float ov2 = __shfl_xor_sync(0xffffffffu, v2, o);
                int   oi2 = __shfl_xor_sync(0xffffffffu, i2, o);
                merge2(v1, i1, v2, i2, ov1, oi1);
                merge2(v1, i1, v2, i2, ov2, oi2);
            }
            if ((lane >> 2) == 0) {
                sv1[wid * 64 + bcol] = v1; si1[wid * 64 + bcol] = i1;
                sv2[wid * 64 + bcol] = v2; si2[wid * 64 + bcol] = i2;
            }
        }
    }
    __syncthreads();
    if (tid < 64) {
        float V1 = sv1[tid]; int I1 = si1[tid];
        float V2 = sv2[tid]; int I2 = si2[tid];
#pragma unroll
        for (int w = 1; w < 8; w++) {
            merge2(V1, I1, V2, I2, sv1[w * 64 + tid], si1[w * 64 + tid]);
            merge2(V1, I1, V2, I2, sv2[w * 64 + tid], si2[w * 64 + tid]);
        }
        g_pm[blockIdx.x][tid]  = V1;
        g_pa[blockIdx.x][tid]  = I1;
        g_pm2[blockIdx.x][tid] = V2;
        g_pa2[blockIdx.x][tid] = I2;
        tmx[tid] = V1;
    }
    __syncthreads();
#pragma unroll
    for (int nt = 0; nt < 8; nt++) {
#pragma unroll
        for (int c = 0; c < 2; c++) {
            int bcol = nt * 8 + (lane & 3) * 2 + c;
            float tm = tmx[bcol];
            float s = expf(acc[nt][c] - tm) + expf(acc[nt][2 + c] - tm);
#pragma unroll
            for (int o = 4; o <= 16; o <<= 1)
                s += __shfl_xor_sync(0xffffffffu, s, o);
            if ((lane >> 2) == 0) sv1[wid * 64 + bcol] = s;
        }
    }
    __syncthreads();
    if (tid < 64) {
        float s = 0.f;
#pragma unroll
        for (int w = 0; w < 8; w++) s += sv1[w * 64 + tid];
        g_ps[blockIdx.x][tid] = s;
    }
}

// ---------------- lsm merge body ----------------
__device__ __forceinline__ void lsm_merge_body(
    float* pool, int b, int step, int tid,
    const float* __restrict__ Wl, const float* __restrict__ bl)
{
    float* sm    = pool;
    float* ssum  = pool + 256;
    float* cv    = pool + 512;
    int*   ci    = (int*)(pool + 1024);
    int*   cand8 = (int*)(pool + 1536);
    float* exv   = pool + 1544;
    int*   exi   = (int*)(pool + 1552);

    float m = -1e30f;
    if (tid < NTILE) m = g_pm[tid][b];
    sm[tid] = m;
    __syncthreads();
    for (int o = 128; o > 0; o >>= 1) {
        if (tid < o) sm[tid] = fmaxf(sm[tid], sm[tid + o]);
        __syncthreads();
    }
    float M = sm[0];

    float s = 0.f;
    if (tid < NTILE) s = g_ps[tid][b] * expf(g_pm[tid][b] - M);
    ssum[tid] = s;
    __syncthreads();
    for (int o = 128; o > 0; o >>= 1) {
        if (tid < o) ssum[tid] += ssum[tid + o];
        __syncthreads();
    }
    if (tid == 0) g_lse[step * BB + b] = M + logf(ssum[0]);

    if (tid < NTILE) { cv[tid] = g_pm[tid][b];        ci[tid] = g_pa[tid][b]; }
    else             { cv[tid] = -1e30f;              ci[tid] = 0x7fffffff; }
    if (tid < NTILE) { cv[256 + tid] = g_pm2[tid][b]; ci[256 + tid] = g_pa2[tid][b]; }
    else             { cv[256 + tid] = -1e30f;        ci[256 + tid] = 0x7fffffff; }
    __syncthreads();
    for (int cdx = tid; cdx < 512; cdx += 256) {
        int mi = ci[cdx];
        if (mi != 0x7fffffff) {
            float mv = cv[cdx];
            int rank = 0;
            for (int j = 0; j < 512; j++) {
                float v = cv[j]; int ij = ci[j];
                if (v > mv || (v == mv && ij < mi)) rank++;
            }
            if (rank < 8) cand8[rank] = mi;
        }
    }
    __syncthreads();
    {
        int warp = tid >> 5, lane = tid & 31;
        int row = cand8[warp];
        const float* wrow = Wl + (size_t)row * H3;
        const float* arow = g_lin + b * H3;
        float p = 0.f;
#pragma unroll 4
        for (int k = lane; k < H3; k += 32) p += wrow[k] * arow[k];
#pragma unroll
        for (int o = 16; o > 0; o >>= 1)
            p += __shfl_down_sync(0xffffffffu, p, o);
        if (lane == 0) { exv[warp] = p + bl[row]; exi[warp] = row; }
    }
    __syncthreads();
    if (tid == 0) {
        float bv = exv[0]; int bi = exi[0];
#pragma unroll
        for (int w = 1; w < 8; w++) {
            if (exv[w] > bv || (exv[w] == bv && exi[w] < bi)) { bv = exv[w]; bi = exi[w]; }
        }
        g_tok[b] = bi;
    }
}

// ---------------- final-step lsm ----------------
__global__ __launch_bounds__(256) void lsm_argmax_kernel(
    const float* __restrict__ Wl, const float* __restrict__ bl, int step)
{
    __shared__ float pool[1560];
    lsm_merge_body(pool, blockIdx.x, step, threadIdx.x, Wl, bl);
}

// ---------------- final: normalize last step only ----------------
__global__ __launch_bounds__(256) void lsm_norm_last_kernel(float* __restrict__ out)
{
    size_t idx = (size_t)blockIdx.x * 256 + threadIdx.x;   // over BB*KY/4
    int b = (int)(idx / (KY / 4));
    float lse = g_lse[(TY - 1) * BB + b];
    float4* o = (float4*)(out + (size_t)(TY - 1) * BB * KY);
    float4 v = o[idx];
    v.x -= lse; v.y -= lse; v.z -= lse; v.w -= lse;
    o[idx] = v;
}

// ---------------- fused decoder step: lsm(s-1) || q-proj -> attn -> decgru ----------------
__global__ __launch_bounds__(256, 1) void step_kernel(
    int s,
    const float* __restrict__ Wl,  const float* __restrict__ bl,
    const float* __restrict__ W_a1, const float* __restrict__ W_a2,
    const float* __restrict__ b_a2, const float* __restrict__ dec_emb,
    const float* __restrict__ Wih, const float* __restrict__ Whh,
    const float* __restrict__ bih, const float* __restrict__ bhh)
{
    __shared__ float pool[128 * 65 + 12 * 128];
    int tid = threadIdx.x;
    int cta = blockIdx.x;

    if (cta < 64) {
        if (s > 0) lsm_merge_body(pool, cta, s - 1, tid, Wl, bl);
    } else {
        float (*hs)[65] = (float(*)[65])pool;
        float* wsj = pool + 128 * 65;
        int b = tid & 63, jl = tid >> 6;
        int j0 = (cta - 64) * 8;
        const float* hcur = g_hd[s & 1];
        float acc0 = 0.f, acc1 = 0.f;
        for (int kb = 0; kb < 4; kb++) {
            int kbase = kb * 128;
#pragma unroll
            for (int r = 0; r < 32; r++) {
                int i = tid + r * 256;
                int kk = i & 127, bb2 = i >> 7;
                hs[kk][bb2] = hcur[bb2 * HH + kbase + kk];
            }
#pragma unroll
            for (int r = 0; r < 4; r++) {
                int i = tid + r * 256;
                int kk = i & 127, rr = i >> 7;
                wsj[rr * 128 + kk] = W_a1[(size_t)(j0 + rr) * H3 + kbase + kk];
            }
            __syncthreads();
#pragma unroll 8
            for (int k = 0; k < 128; k += 4) {
                float4 w0 = *(const float4*)&wsj[jl * 128 + k];
                float4 w1 = *(const float4*)&wsj[(4 + jl) * 128 + k];
                float h0 = hs[k][b], h1 = hs[k + 1][b], h2 = hs[k + 2][b], h3 = hs[k + 3][b];
                acc0 += h0 * w0.x + h1 * w0.y + h2 * w0.z + h3 * w0.w;
                acc1 += h0 * w1.x + h1 * w1.y + h2 * w1.z + h3 * w1.w;
            }
            __syncthreads();
        }
        g_q[b * HH + j0 + jl]     = acc0;
        g_q[b * HH + j0 + 4 + jl] = acc1;
    }

    grid_barrier(2, 127, tid);

    {
        float* qs  = pool;
        float* was = pool + 512;
        float* ss  = pool + 1024;
        float* wgt = pool + 1088;
        int b = cta >> 1, half = cta & 1;
        int lane = tid & 31, warp = tid >> 5;

        if (half == 0) {
            int tok = __ldcg(&g_tok[b]);
            for (int i = tid; i < EE; i += 256)
                g_rnnin[b * RNNIN + i] = dec_emb[(size_t)tok * EE + i];
        }
        for (int i = tid; i < HH; i += 256) {
            qs[i] = __ldcg(&g_q[b * HH + i]);
            was[i] = W_a2[i];
        }
        __syncthreads();

        for (int tt = 0; tt < 8; tt++) {
            int t = warp * 8 + tt;
            const float* Prow = g_P + (size_t)(t * BB + b) * HH;
            float p = 0.f;
#pragma unroll 4
            for (int jj = lane; jj < HH; jj += 32)
                p += was[jj] * tanhf(qs[jj] + Prow[jj]);
#pragma unroll
            for (int o = 16; o > 0; o >>= 1)
                p += __shfl_down_sync(0xffffffffu, p, o);
            if (lane == 0) ss[t] = p + b_a2[0];
        }
        __syncthreads();

        if (tid < 32) {
            float v0 = ss[tid], v1 = ss[tid + 32];
            float m = fmaxf(v0, v1);
#pragma unroll
            for (int o = 16; o > 0; o >>= 1)
                m = fmaxf(m, __shfl_xor_sync(0xffffffffu, m, o));
            float e0 = expf(v0 - m), e1 = expf(v1 - m);
            float s2 = e0 + e1;
#pragma unroll
            for (int o = 16; o > 0; o >>= 1)
                s2 += __shfl_xor_sync(0xffffffffu, s2, o);
            wgt[tid] = e0 / s2;
            wgt[tid + 32] = e1 / s2;
        }
        __syncthreads();

        int i0 = half * 512;
        for (int ii = tid; ii < 512; ii += 256) {
            int i = i0 + ii;
            float c = 0.f;
#pragma unroll 8
            for (int t = 0; t < TX; t++)
                c += wgt[t] * g_enc[(size_t)(t * BB + b) * CTXD + i];
            g_rnnin[b * RNNIN + EE + i] = c;
            g_lin[b * H3 + HH + i] = c;
            g_ah[b * H3 + HH + i] = __float2half_rn(c);
        }
    }

    grid_barrier(2, 127, tid);

    {
        float (*xs)[65] = (float(*)[65])pool;
        float* ws = pool + 128 * 65;
        int b = tid & 63;
        int jl = tid >> 6;
        int j0 = cta * 4;
        int j = j0 + jl;
        int par = s & 1;
        const float* hin = g_hd[par];
        float* hout = g_hd[par ^ 1];

        float ar = 0.f, az = 0.f, anx = 0.f, anh = 0.f;

        for (int kb = 0; kb < 10; kb++) {
            int kbase = kb * 128;
#pragma unroll
            for (int r = 0; r < 32; r++) {
                int i = tid + r * 256;
                int kk = i & 127, bb2 = i >> 7;
                xs[kk][bb2] = __ldcg(&g_rnnin[bb2 * RNNIN + kbase + kk]);
            }
#pragma unroll
            for (int r = 0; r < 6; r++) {
                int i = tid + r * 256;
                int kk = i & 127, rr = i >> 7;
                int g = rr >> 2, jloc = rr & 3;
                ws[rr * 128 + kk] = Wih[(size_t)(g * HH + j0 + jloc) * RNNIN + kbase + kk];
            }
            __syncthreads();
#pragma unroll 8
            for (int k = 0; k < 128; k += 4) {
                float4 wr = *(const float4*)&ws[jl * 128 + k];
                float4 wz = *(const float4*)&ws[(4 + jl) * 128 + k];
                float4 wn = *(const float4*)&ws[(8 + jl) * 128 + k];
                float x0 = xs[k][b], x1 = xs[k + 1][b], x2 = xs[k + 2][b], x3 = xs[k + 3][b];
                ar += x0 * wr.x + x1 * wr.y + x2 * wr.z + x3 * wr.w;
                az += x0 * wz.x + x1 * wz.y + x2 * wz.z + x3 * wz.w;
                anx += x0 * wn.x + x1 * wn.y + x2 * wn.z + x3 * wn.w;
            }
            __syncthreads();
        }

        for (int kb = 0; kb < 4; kb++) {
            int kbase = kb * 128;
#pragma unroll
            for (int r = 0; r < 32; r++) {
                int i = tid + r * 256;
                int kk = i & 127, bb2 = i >> 7;
                xs[kk][bb2] = hin[bb2 * HH + kbase + kk];
            }
#pragma unroll
            for (int r = 0; r < 6; r++) {
                int i = tid + r * 256;
                int kk = i & 127, rr = i >> 7;
                int g = rr >> 2, jloc = rr & 3;
                ws[rr * 128 + kk] = Whh[(size_t)(g * HH + j0 + jloc) * HH + kbase + kk];
            }
            __syncthreads();
#pragma unroll 8
            for (int k = 0; k < 128; k += 4) {
                float4 wr = *(const float4*)&ws[jl * 128 + k];
                float4 wz = *(const float4*)&ws[(4 + jl) * 128 + k];
                float4 wn = *(const float4*)&ws[(8 + jl) * 128 + k];
                float x0 = xs[k][b], x1 = xs[k + 1][b], x2 = xs[k + 2][b], x3 = xs[k + 3][b];
                ar += x0 * wr.x + x1 * wr.y + x2 * wr.z + x3 * wr.w;
                az += x0 * wz.x + x1 * wz.y + x2 * wz.z + x3 * wz.w;
                anh += x0 * wn.x + x1 * wn.y + x2 * wn.z + x3 * wn.w;
            }
            __syncthreads();
        }

        float r = sigm(ar + bih[j] + bhh[j]);
        float z = sigm(az + bih[HH + j] + bhh[HH + j]);
        float n = tanhf(anx + bih[2 * HH + j] + r * (anh + bhh[2 * HH + j]));
        float hold = hin[b * HH + j];
        float h2 = (1.f - z) * n + z * hold;
        hout[b * HH + j] = h2;
        g_lin[b * H3 + j] = h2;
        g_ah[b * H3 + j] = __float2half_rn(h2);
    }
}

// ---------------- generic SGEMM (clock canary: ~158us at normal clocks) ----------------
__global__ __launch_bounds__(256) void sgemm_kernel(
    const float* __restrict__ A, const int* __restrict__ gather,
    const float* __restrict__ W, int ldw,
    const float* __restrict__ bias,
    float* __restrict__ C, int N, int K)
{
    __shared__ float As[16][64];
    __shared__ float Ws[16][128];
    int tid = threadIdx.x;
    int m0 = blockIdx.y * 64;
    int n0 = blockIdx.x * 128;
    int tx = tid & 15, ty = tid >> 4;

    float acc[4][8];
#pragma unroll
    for (int i = 0; i < 4; i++)
#pragma unroll
        for (int j = 0; j < 8; j++) acc[i][j] = 0.f;

    int lrow = tid >> 2;
    int lk = (tid & 3) * 4;
    int arow = m0 + lrow;
    int aphys = gather ? gather[arow] : arow;
    const float* Aptr = A + (size_t)aphys * K + lk;

    for (int k0 = 0; k0 < K; k0 += 16) {
        float4 av = *(const float4*)(Aptr + k0);
        As[lk + 0][lrow] = av.x; As[lk + 1][lrow] = av.y;
        As[lk + 2][lrow] = av.z; As[lk + 3][lrow] = av.w;
#pragma unroll
        for (int r = 0; r < 2; r++) {
            int nrow = lrow + r * 64;
            float4 wv = *(const float4*)(W + (size_t)(n0 + nrow) * ldw + k0 + lk);
            Ws[lk + 0][nrow] = wv.x; Ws[lk + 1][nrow] = wv.y;
            Ws[lk + 2][nrow] = wv.z; Ws[lk + 3][nrow] = wv.w;
        }
        __syncthreads();
#pragma unroll
        for (int kk = 0; kk < 16; kk++) {
            float a[4];
#pragma unroll
            for (int i = 0; i < 4; i++) a[i] = As[kk][ty * 4 + i];
            float4 b0 = *(const float4*)&Ws[kk][tx * 8];
            float4 b1 = *(const float4*)&Ws[kk][tx * 8 + 4];
            float bb8[8] = { b0.x, b0.y, b0.z, b0.w, b1.x, b1.y, b1.z, b1.w };
#pragma unroll
            for (int i = 0; i < 4; i++)
#pragma unroll
                for (int j = 0; j < 8; j++) acc[i][j] += a[i] * bb8[j];
        }
        __syncthreads();
    }
#pragma unroll
    for (int i = 0; i < 4; i++) {
        int m = m0 + ty * 4 + i;
        float* crow = C + (size_t)m * N + n0 + tx * 8;
#pragma unroll
        for (int j = 0; j < 8; j++) {
            float v = acc[i][j];
            if (bias) v += bias[n0 + tx * 8 + j];
            crow[j] = v;
        }
    }
}

// ---------------- persistent encoder ----------------
#define ENC_WS_FLOATS (24 * 512)
#define ENC_SMEM ((ENC_WS_FLOATS + 128 * 65) * 4)

__global__ __launch_bounds__(512, 1) void enc_persist_kernel(
    const float* __restrict__ Whh_f, const float* __restrict__ bhh_f,
    const float* __restrict__ Whh_b, const float* __restrict__ bhh_b)
{
    extern __shared__ float smf_[];
    float* ws = smf_;
    float (*hs)[65] = (float(*)[65])(smf_ + ENC_WS_FLOATS);

    int dir = blockIdx.y;
    const float* Whh = dir ? Whh_b : Whh_f;
    const float* bhh = dir ? bhh_b : bhh_f;
    int tid = threadIdx.x;
    int b = tid & 63;
    int jl = tid >> 6;
    int j0 = blockIdx.x * 8;
    int j = j0 + jl;
    int colofs = dir ? HH : 0;

    for (int idx = tid; idx < ENC_WS_FLOATS; idx += 512) {
        int rr = idx >> 9, kk = idx & 511;
        ws[idx] = Whh[(size_t)((rr >> 3) * HH + j0 + (rr & 7)) * HH + kk];
    }
    float br = bhh[j], bz = bhh[HH + j], bn = bhh[2 * HH + j];
    __syncthreads();

    for (int t = 0; t < TX; t++) {
        int par = t & 1;
        int row = dir ? (TX - 1 - t) : t;
        const float* gi = (dir ? g_gi_b : g_gi_f) + (size_t)row * BB * H3;
        const float* hin = g_henc[dir][par];
        float* hout = g_henc[dir][par ^ 1];

        float dr = 0.f, dz = 0.f, dn = 0.f;
        for (int kb = 0; kb < 4; kb++) {
            int kbase = kb * 128;
#pragma unroll
            for (int r = 0; r < 16; r++) {
                int i = tid + r * 512;
                int kk = i & 127, bb2 = i >> 7;
                hs[kk][bb2] = __ldcg(&hin[bb2 * HH + kbase + kk]);
            }
            __syncthreads();
            const float* wr4 = ws + jl * 512 + kbase;
            const float* wz4 = ws + (8 + jl) * 512 + kbase;
            const float* wn4 = ws + (16 + jl) * 512 + kbase;
#pragma unroll 8
            for (int k = 0; k < 128; k += 4) {
                float4 wr = *(const float4*)(wr4 + k);
                float4 wz = *(const float4*)(wz4 + k);
                float4 wn = *(const float4*)(wn4 + k);
                float h0 = hs[k][b], h1 = hs[k + 1][b], h2v = hs[k + 2][b], h3v = hs[k + 3][b];
                dr += h0 * wr.x + h1 * wr.y + h2v * wr.z + h3v * wr.w;
                dz += h0 * wz.x + h1 * wz.y + h2v * wz.z + h3v * wz.w;
                dn += h0 * wn.x + h1 * wn.y + h2v * wn.z + h3v * wn.w;
            }
            __syncthreads();
        }

        const float* girow = gi + b * H3;
        float r = sigm(girow[j] + dr + br);
        float z = sigm(girow[HH + j] + dz + bz);
        float n = tanhf(girow[2 * HH + j] + r * (dn + bn));
        float hold = __ldcg(&hin[b * HH + j]);
        float h2 = (1.f - z) * n + z * hold;
        __stcg(&hout[b * HH + j], h2);
        g_enc[(size_t)(row * BB + b) * CTXD + colofs + j] = h2;

        if (t + 1 < TX) grid_barrier(dir, 63, tid);
    }
}

// ---------------- column projection (hidden init only) ----------------
__global__ __launch_bounds__(512) void colproj_kernel(
    const float* __restrict__ src, const float* __restrict__ W, int ldw,
    const float* __restrict__ bias, float* __restrict__ dst, int act)
{
    __shared__ float hs[128][65];
    __shared__ float ws[8][128];
    int tid = threadIdx.x;
    int b = tid & 63;
    int jl = tid >> 6;
    int j0 = blockIdx.x * 8;
    int j = j0 + jl;

    float acc = 0.f;
    for (int kb = 0; kb < 4; kb++) {
        int kbase = kb * 128;
#pragma unroll
        for (int r = 0; r < 16; r++) {
            int i = tid + r * 512;
            int kk = i & 127, bb2 = i >> 7;
            hs[kk][bb2] = src[bb2 * HH + kbase + kk];
        }
#pragma unroll
        for (int r = 0; r < 2; r++) {
            int i = tid + r * 512;
            int kk = i & 127, rr = i >> 7;
            ws[rr][kk] = W[(size_t)(j0 + rr) * ldw + kbase + kk];
        }
        __syncthreads();
#pragma unroll 8
        for (int k = 0; k < 128; k += 4) {
            float4 wv = *(const float4*)&ws[jl][k];
            acc += hs[k][b] * wv.x + hs[k + 1][b] * wv.y
                 + hs[k + 2][b] * wv.z + hs[k + 3][b] * wv.w;
        }
        __syncthreads();
    }
    if (bias) acc += bias[j];
    if (act) acc = tanhf(acc);
    dst[b * HH + j] = acc;
}

// ---------------- host launch ----------------
extern "C" void kernel_launch(void* const* d_in, const int* in_sizes, int n_in,
                              void* d_out, int out_size)
{
    const int*   inputs  = (const int*)d_in[0];
    const float* enc_emb = (const float*)d_in[2];
    const float* W_ih_f  = (const float*)d_in[3];
    const float* W_hh_f  = (const float*)d_in[4];
    const float* b_ih_f  = (const float*)d_in[5];
    const float* b_hh_f  = (const float*)d_in[6];
    const float* W_ih_b  = (const float*)d_in[7];
    const float* W_hh_b  = (const float*)d_in[8];
    const float* b_ih_b  = (const float*)d_in[9];
    const float* b_hh_b  = (const float*)d_in[10];
    const float* W_init  = (const float*)d_in[11];
    const float* b_init  = (const float*)d_in[12];
    const float* dec_emb = (const float*)d_in[13];
    const float* W_ih_d  = (const float*)d_in[14];
    const float* W_hh_d  = (const float*)d_in[15];
    const float* b_ih_d  = (const float*)d_in[16];
    const float* b_hh_d  = (const float*)d_in[17];
    const float* W_lsm   = (const float*)d_in[18];
    const float* b_lsm   = (const float*)d_in[19];
    const float* W_a1    = (const float*)d_in[20];
    const float* b_a1    = (const float*)d_in[21];
    const float* W_a2    = (const float*)d_in[22];
    const float* b_a2    = (const float*)d_in[23];
    float* out = (float*)d_out;

    static float* p_P    = nullptr;
    static float* p_gi_f = nullptr;
    static float* p_gi_b = nullptr;
    static float* p_enc  = nullptr;
    static float* p_hd   = nullptr;
    static float* p_henc = nullptr;
    static cudaStream_t s2 = nullptr;
    static cudaEvent_t ev_root, ev_w;
    if (!p_gi_f) {
        cudaGetSymbolAddress((void**)&p_gi_f, g_gi_f);
        cudaGetSymbolAddress((void**)&p_gi_b, g_gi_b);
        cudaGetSymbolAddress((void**)&p_enc,  g_enc);
        cudaGetSymbolAddress((void**)&p_P,    g_P);
        cudaGetSymbolAddress((void**)&p_hd,   g_hd);
        cudaGetSymbolAddress((void**)&p_henc, g_henc);
        cudaFuncSetAttribute(logits_mma_kernel,
                             cudaFuncAttributeMaxDynamicSharedMemorySize, LG_SMEM_TOTAL);
        cudaFuncSetAttribute(enc_persist_kernel,
                             cudaFuncAttributeMaxDynamicSharedMemorySize, ENC_SMEM);
        cudaStreamCreateWithFlags(&s2, cudaStreamNonBlocking);
        cudaEventCreateWithFlags(&ev_root, cudaEventDisableTiming);
        cudaEventCreateWithFlags(&ev_w,    cudaEventDisableTiming);
    }

    cudaEventRecord(ev_root, 0);

    init_kernel<<<128, 256>>>();

    sgemm_kernel<<<dim3(H3 / 128, TX * BB / 64), 256>>>(
        enc_emb, inputs, W_ih_f, EE, b_ih_f, p_gi_f, H3, EE);
    sgemm_kernel<<<dim3(H3 / 128, TX * BB / 64), 256>>>(
        enc_emb, inputs, W_ih_b, EE, b_ih_b, p_gi_b, H3, EE);

    enc_persist_kernel<<<dim3(64, 2), 512, ENC_SMEM>>>(
        W_hh_f, b_hh_f, W_hh_b, b_hh_b);

    // convw on stream 2 (executes from t=0 via ev_root)
    cudaStreamWaitEvent(s2, ev_root, 0);
    convw_kernel<<<(int)(((size_t)KY * H3 / 4) / 256), 256, 0, s2>>>(W_lsm);
    cudaEventRecord(ev_w, s2);

    sgemm_kernel<<<dim3(HH / 128, TX * BB / 64), 256>>>(
        p_enc, nullptr, W_a1 + HH, H3, b_a1, p_P, HH, CTXD);

    colproj_kernel<<<64, 512>>>(p_henc + 2 * BB * HH, W_init, HH, b_init, p_hd, 1);

    cudaStreamWaitEvent(0, ev_w, 0);

    for (int s = 0; s < TY; s++) {
        step_kernel<<<128, 256>>>(s, W_lsm, b_lsm, W_a1, W_a2, b_a2, dec_emb,
                                  W_ih_d, W_hh_d, b_ih_d, b_hh_d);
        logits_mma_kernel<<<NTILE, 256, LG_SMEM_TOTAL>>>(b_lsm, out, s);
    }

    // final step's lse then normalize only step 31
    lsm_argmax_kernel<<<64, 256>>>(W_lsm, b_lsm, TY - 1);
    lsm_norm_last_kernel<<<BB * KY / 4 / 256, 256>>>(out);
}

// round 17
// speedup vs baseline: 1.0364x; 1.0364x over previous
#include <cuda_runtime.h>
#include <cuda_bf16.h>
#include <cuda_fp16.h>
#include <math.h>
#include <stdint.h>

// Problem constants
#define TX 64
#define BB 64
#define TY 32
#define EE 256
#define HH 512
#define H3 1536
#define KY 32000
#define CTXD 1024      // 2H
#define RNNIN 1280     // E + 2H
#define NTILE (KY / 128)   // 250 vocab tiles (M=128)

// ---------------- device scratch ----------------
__device__ float g_gi_f[TX * BB * H3];
__device__ float g_gi_b[TX * BB * H3];
__device__ float g_henc[2][2][BB * HH];
__device__ float g_enc[TX * BB * CTXD];
__device__ float g_P[TX * BB * HH];
__device__ float g_hd[2][BB * HH];
__device__ float g_q[BB * HH];
__device__ float g_lin[BB * H3];     // fp32 [h2, context] for exact-argmax rescue
__device__ float g_rnnin[BB * RNNIN];
__device__ int   g_tok[BB];
__device__ float g_lse[TY * BB];

__device__ __half g_wh[(size_t)KY * H3];   // fp16(W_lsm)
__device__ __half g_ah[BB * H3];           // fp16 of [h2, context]

// per-tile softmax partials (top-2 + sum)
__device__ float g_pm[NTILE][BB];
__device__ int   g_pa[NTILE][BB];
__device__ float g_pm2[NTILE][BB];
__device__ int   g_pa2[NTILE][BB];
__device__ float g_ps[NTILE][BB];

__device__ volatile unsigned g_bar_gen[3];
__device__ unsigned g_bar_cnt[3];

__device__ __forceinline__ float sigm(float x) { return 1.0f / (1.0f + expf(-x)); }

// ---------------- init ----------------
__global__ void init_kernel() {
    int i = blockIdx.x * blockDim.x + threadIdx.x;
    if (i < BB * HH) {
        g_henc[0][0][i] = 0.f;
        g_henc[1][0][i] = 0.f;
    }
    if (i < BB) g_tok[i] = 1;
    if (i < 3) { g_bar_gen[i] = 0; g_bar_cnt[i] = 0; }
}

// ---------------- W_lsm -> fp16 ----------------
__global__ __launch_bounds__(256) void convw_kernel(const float* __restrict__ W) {
    size_t i = (size_t)blockIdx.x * blockDim.x + threadIdx.x;
    const float4* W4 = (const float4*)W;
    float4 v = __ldcs(&W4[i]);
    __half2* H2 = reinterpret_cast<__half2*>(g_wh);
    H2[2 * i]     = __halves2half2(__float2half_rn(v.x), __float2half_rn(v.y));
    H2[2 * i + 1] = __halves2half2(__float2half_rn(v.z), __float2half_rn(v.w));
}

// ---------------- mma.sync fp16 helper ----------------
__device__ __forceinline__ void mma16816h(float* d, const uint32_t* a, uint32_t b0, uint32_t b1)
{
    asm volatile(
        "mma.sync.aligned.m16n8k16.row.col.f32.f16.f16.f32 "
        "{%0,%1,%2,%3}, {%4,%5,%6,%7}, {%8,%9}, {%0,%1,%2,%3};"
        : "+f"(d[0]), "+f"(d[1]), "+f"(d[2]), "+f"(d[3])
        : "r"(a[0]), "r"(a[1]), "r"(a[2]), "r"(a[3]), "r"(b0), "r"(b1));
}

__device__ __forceinline__ void merge2(float& v1, int& i1, float& v2, int& i2, float v, int i)
{
    if (v > v1 || (v == v1 && i < i1)) { v2 = v1; i2 = i1; v1 = v; i1 = i; }
    else if (v > v2 || (v == v2 && i < i2)) { v2 = v; i2 = i; }
}

// ---------------- software grid barrier ----------------
__device__ __forceinline__ void grid_barrier(int slot, int nm1, int tid)
{
    __threadfence();
    __syncthreads();
    if (tid == 0) {
        unsigned gen = g_bar_gen[slot];
        unsigned t = atomicAdd(&g_bar_cnt[slot], 1u);
        if (t == (unsigned)nm1) {
            g_bar_cnt[slot] = 0u;
            __threadfence();
            g_bar_gen[slot] = gen + 1u;
        } else {
            while (g_bar_gen[slot] == gen) __nanosleep(40);
        }
    }
    __syncthreads();
}

// ---------------- logits GEMM: M=128 tiles, 250 CTAs, 2 CTAs/SM, 3-stage ----------------
// Output stores are streaming (__stcs) so fp16 W stays L2-resident across steps.
#define LG_KC 64
#define LG_ROWB 144
#define LG_W_BYTES (128 * LG_ROWB)                 // 18432
#define LG_A_BYTES (64 * LG_ROWB)                  // 9216
#define LG_STAGE (LG_W_BYTES + LG_A_BYTES)         // 27648
#define LG_NSTAGE 3
#define LG_SMEM_TOTAL (LG_NSTAGE * LG_STAGE)       // 82944

__global__ __launch_bounds__(256, 2) void logits_mma_kernel(
    const float* __restrict__ b_lsm, float* __restrict__ out, int step)
{
    extern __shared__ char smem[];
    int tid = threadIdx.x;
    int wid = tid >> 5, lane = tid & 31;
    int vb = blockIdx.x * 128;

    auto load_chunk = [&](int kc, int buf) {
        char* base = smem + buf * LG_STAGE;
        {
            char* dst = base;
            const __half* sh = g_wh + (size_t)vb * H3 + kc * LG_KC;
#pragma unroll
            for (int it = 0; it < 4; it++) {
                int idx = tid + it * 256;
                int r = idx >> 3, c = idx & 7;
                size_t gofs = (size_t)r * H3 + c * 8;
                uint32_t so = (uint32_t)(r * LG_ROWB + c * 16);
                uint32_t d1 = (uint32_t)__cvta_generic_to_shared(dst + so);
                asm volatile("cp.async.cg.shared.global [%0], [%1], 16;" :: "r"(d1), "l"(sh + gofs));
            }
        }
        {
            char* dst = base + LG_W_BYTES;
            const __half* sa = g_ah + kc * LG_KC;
#pragma unroll
            for (int it = 0; it < 2; it++) {
                int idx = tid + it * 256;
                int r = idx >> 3, c = idx & 7;
                size_t gofs = (size_t)r * H3 + c * 8;
                uint32_t so = (uint32_t)(r * LG_ROWB + c * 16);
                uint32_t d1 = (uint32_t)__cvta_generic_to_shared(dst + so);
                asm volatile("cp.async.cg.shared.global [%0], [%1], 16;" :: "r"(d1), "l"(sa + gofs));
            }
        }
        asm volatile("cp.async.commit_group;" ::: "memory");
    };

    float acc[8][4];
#pragma unroll
    for (int nt = 0; nt < 8; nt++)
#pragma unroll
        for (int i = 0; i < 4; i++) acc[nt][i] = 0.f;

    int m0 = wid * 16;
    int krow = lane >> 2;
    int kcol4 = (lane & 3) * 4;

    const int NC = H3 / LG_KC;   // 24
    load_chunk(0, 0);
    load_chunk(1, 1);
    load_chunk(2, 2);

    int buf = 0;
    for (int c = 0; c < NC; c++) {
        if (c <= NC - 3) {
            asm volatile("cp.async.wait_group 2;" ::: "memory");
        } else if (c == NC - 2) {
            asm volatile("cp.async.wait_group 1;" ::: "memory");
        } else {
            asm volatile("cp.async.wait_group 0;" ::: "memory");
        }
        __syncthreads();

        char* base = smem + buf * LG_STAGE;
        const char* wh = base;
        const char* ab = base + LG_W_BYTES;

#pragma unroll
        for (int kt = 0; kt < 4; kt++) {
            int kb = kt * 32 + kcol4;
            uint32_t wf[4];
            int ro = (m0 + krow) * LG_ROWB + kb;
            wf[0] = *(const uint32_t*)(wh + ro);
            wf[1] = *(const uint32_t*)(wh + ro + 8 * LG_ROWB);
            wf[2] = *(const uint32_t*)(wh + ro + 16);
            wf[3] = *(const uint32_t*)(wh + ro + 8 * LG_ROWB + 16);
#pragma unroll
            for (int nt = 0; nt < 8; nt++) {
                int rb = (nt * 8 + krow) * LG_ROWB + kb;
                uint32_t b0 = *(const uint32_t*)(ab + rb);
                uint32_t b1 = *(const uint32_t*)(ab + rb + 16);
                mma16816h(acc[nt], wf, b0, b1);
            }
        }
        __syncthreads();
        if (c + 3 < NC) load_chunk(c + 3, buf);
        buf = (buf + 1 == LG_NSTAGE) ? 0 : buf + 1;
    }

    // ---- epilogue: bias + transpose-stage + coalesced streaming store ----
    float* st = (float*)smem;                       // [64][132]
#pragma unroll
    for (int h = 0; h < 2; h++) {
        int vloc = m0 + krow + h * 8;
        float bias = b_lsm[vb + vloc];
#pragma unroll
        for (int nt = 0; nt < 8; nt++) {
            int b0 = nt * 8 + (lane & 3) * 2;
            float x0 = acc[nt][h * 2 + 0] + bias;
            float x1 = acc[nt][h * 2 + 1] + bias;
            acc[nt][h * 2 + 0] = x0;
            acc[nt][h * 2 + 1] = x1;
            st[b0 * 132 + vloc]       = x0;
            st[(b0 + 1) * 132 + vloc] = x1;
        }
    }
    __syncthreads();
    {
        float* obase = out + (size_t)step * BB * KY + vb;
        int col = tid & 127;
        int rofs = tid >> 7;
#pragma unroll 8
        for (int it = 0; it < 32; it++) {
            int r = it * 2 + rofs;
            __stcs(&obase[(size_t)r * KY + col], st[r * 132 + col]);
        }
    }

    // ---- per-tile top-2 + sum partials ----
    float* sv1 = (float*)(smem + 33792);
    int*   si1 = (int*)(smem + 35840);
    float* sv2 = (float*)(smem + 37888);
    int*   si2 = (int*)(smem + 39936);
    float* tmx = (float*)(smem + 41984);

    int vbase = vb + m0 + krow;
#pragma unroll
    for (int nt = 0; nt < 8; nt++) {
#pragma unroll
        for (int c = 0; c < 2; c++) {
            int bcol = nt * 8 + (lane & 3) * 2 + c;
            float v1 = acc[nt][c];     int i1 = vbase;
            float v2 = -1e30f;         int i2 = 0x7fffffff;
            merge2(v1, i1, v2, i2, acc[nt][2 + c], vbase + 8);
#pragma unroll
            for (int o = 4; o <= 16; o <<= 1) {
                float ov1 = __shfl_xor_sync(0xffffffffu, v1, o);
                int   oi1 = __shfl_xor_sync(0xffffffffu, i1, o);
                float ov2 = __shfl_xor_sync(0xffffffffu, v2, o);
                int   oi2 = __shfl_xor_sync(0xffffffffu, i2, o);
                merge2(v1, i1, v2, i2, ov1, oi1);
                merge2(v1, i1, v2, i2, ov2, oi2);
            }
            if ((lane >> 2) == 0) {
                sv1[wid * 64 + bcol] = v1; si1[wid * 64 + bcol] = i1;
                sv2[wid * 64 + bcol] = v2; si2[wid * 64 + bcol] = i2;
            }
        }
    }
    __syncthreads();
    if (tid < 64) {
        float V1 = sv1[tid]; int I1 = si1[tid];
        float V2 = sv2[tid]; int I2 = si2[tid];
#pragma unroll
        for (int w = 1; w < 8; w++) {
            merge2(V1, I1, V2, I2, sv1[w * 64 + tid], si1[w * 64 + tid]);
            merge2(V1, I1, V2, I2, sv2[w * 64 + tid], si2[w * 64 + tid]);
        }
        g_pm[blockIdx.x][tid]  = V1;
        g_pa[blockIdx.x][tid]  = I1;
        g_pm2[blockIdx.x][tid] = V2;
        g_pa2[blockIdx.x][tid] = I2;
        tmx[tid] = V1;
    }
    __syncthreads();
#pragma unroll
    for (int nt = 0; nt < 8; nt++) {
#pragma unroll
        for (int c = 0; c < 2; c++) {
            int bcol = nt * 8 + (lane & 3) * 2 + c;
            float tm = tmx[bcol];
            float s = expf(acc[nt][c] - tm) + expf(acc[nt][2 + c] - tm);
#pragma unroll
            for (int o = 4; o <= 16; o <<= 1)
                s += __shfl_xor_sync(0xffffffffu, s, o);
            if ((lane >> 2) == 0) sv1[wid * 64 + bcol] = s;
        }
    }
    __syncthreads();
    if (tid < 64) {
        float s = 0.f;
#pragma unroll
        for (int w = 0; w < 8; w++) s += sv1[w * 64 + tid];
        g_ps[blockIdx.x][tid] = s;
    }
}

// ---------------- lsm merge body ----------------
__device__ __forceinline__ void lsm_merge_body(
    float* pool, int b, int step, int tid,
    const float* __restrict__ Wl, const float* __restrict__ bl)
{
    float* sm    = pool;
    float* ssum  = pool + 256;
    float* cv    = pool + 512;
    int*   ci    = (int*)(pool + 1024);
    int*   cand8 = (int*)(pool + 1536);
    float* exv   = pool + 1544;
    int*   exi   = (int*)(pool + 1552);

    float m = -1e30f;
    if (tid < NTILE) m = g_pm[tid][b];
    sm[tid] = m;
    __syncthreads();
    for (int o = 128; o > 0; o >>= 1) {
        if (tid < o) sm[tid] = fmaxf(sm[tid], sm[tid + o]);
        __syncthreads();
    }
    float M = sm[0];

    float s = 0.f;
    if (tid < NTILE) s = g_ps[tid][b] * expf(g_pm[tid][b] - M);
    ssum[tid] = s;
    __syncthreads();
    for (int o = 128; o > 0; o >>= 1) {
        if (tid < o) ssum[tid] += ssum[tid + o];
        __syncthreads();
    }
    if (tid == 0) g_lse[step * BB + b] = M + logf(ssum[0]);

    if (tid < NTILE) { cv[tid] = g_pm[tid][b];        ci[tid] = g_pa[tid][b]; }
    else             { cv[tid] = -1e30f;              ci[tid] = 0x7fffffff; }
    if (tid < NTILE) { cv[256 + tid] = g_pm2[tid][b]; ci[256 + tid] = g_pa2[tid][b]; }
    else             { cv[256 + tid] = -1e30f;        ci[256 + tid] = 0x7fffffff; }
    __syncthreads();
    for (int cdx = tid; cdx < 512; cdx += 256) {
        int mi = ci[cdx];
        if (mi != 0x7fffffff) {
            float mv = cv[cdx];
            int rank = 0;
            for (int j = 0; j < 512; j++) {
                float v = cv[j]; int ij = ci[j];
                if (v > mv || (v == mv && ij < mi)) rank++;
            }
            if (rank < 8) cand8[rank] = mi;
        }
    }
    __syncthreads();
    {
        int warp = tid >> 5, lane = tid & 31;
        int row = cand8[warp];
        const float* wrow = Wl + (size_t)row * H3;
        const float* arow = g_lin + b * H3;
        float p = 0.f;
#pragma unroll 4
        for (int k = lane; k < H3; k += 32) p += __ldcs(&wrow[k]) * arow[k];
#pragma unroll
        for (int o = 16; o > 0; o >>= 1)
            p += __shfl_down_sync(0xffffffffu, p, o);
        if (lane == 0) { exv[warp] = p + bl[row]; exi[warp] = row; }
    }
    __syncthreads();
    if (tid == 0) {
        float bv = exv[0]; int bi = exi[0];
#pragma unroll
        for (int w = 1; w < 8; w++) {
            if (exv[w] > bv || (exv[w] == bv && exi[w] < bi)) { bv = exv[w]; bi = exi[w]; }
        }
        g_tok[b] = bi;
    }
}

// ---------------- final-step lsm ----------------
__global__ __launch_bounds__(256) void lsm_argmax_kernel(
    const float* __restrict__ Wl, const float* __restrict__ bl, int step)
{
    __shared__ float pool[1560];
    lsm_merge_body(pool, blockIdx.x, step, threadIdx.x, Wl, bl);
}

// ---------------- final: normalize all steps (streaming) ----------------
__global__ __launch_bounds__(256) void lsm_norm_all_kernel(float* __restrict__ out)
{
    size_t idx = (size_t)blockIdx.x * 256 + threadIdx.x;
    int row = (int)(idx / (KY / 4));
    float lse = g_lse[row];
    float4* o = (float4*)out;
    float4 v = __ldcs(&o[idx]);
    v.x -= lse; v.y -= lse; v.z -= lse; v.w -= lse;
    __stcs(&o[idx], v);
}

// ---------------- fused decoder step: lsm(s-1) || q-proj -> attn -> decgru ----------------
__global__ __launch_bounds__(256, 1) void step_kernel(
    int s,
    const float* __restrict__ Wl,  const float* __restrict__ bl,
    const float* __restrict__ W_a1, const float* __restrict__ W_a2,
    const float* __restrict__ b_a2, const float* __restrict__ dec_emb,
    const float* __restrict__ Wih, const float* __restrict__ Whh,
    const float* __restrict__ bih, const float* __restrict__ bhh)
{
    __shared__ float pool[128 * 65 + 12 * 128];
    int tid = threadIdx.x;
    int cta = blockIdx.x;

    if (cta < 64) {
        if (s > 0) lsm_merge_body(pool, cta, s - 1, tid, Wl, bl);
    } else {
        float (*hs)[65] = (float(*)[65])pool;
        float* wsj = pool + 128 * 65;
        int b = tid & 63, jl = tid >> 6;
        int j0 = (cta - 64) * 8;
        const float* hcur = g_hd[s & 1];
        float acc0 = 0.f, acc1 = 0.f;
        for (int kb = 0; kb < 4; kb++) {
            int kbase = kb * 128;
#pragma unroll
            for (int r = 0; r < 32; r++) {
                int i = tid + r * 256;
                int kk = i & 127, bb2 = i >> 7;
                hs[kk][bb2] = hcur[bb2 * HH + kbase + kk];
            }
#pragma unroll
            for (int r = 0; r < 4; r++) {
                int i = tid + r * 256;
                int kk = i & 127, rr = i >> 7;
                wsj[rr * 128 + kk] = W_a1[(size_t)(j0 + rr) * H3 + kbase + kk];
            }
            __syncthreads();
#pragma unroll 8
            for (int k = 0; k < 128; k += 4) {
                float4 w0 = *(const float4*)&wsj[jl * 128 + k];
                float4 w1 = *(const float4*)&wsj[(4 + jl) * 128 + k];
                float h0 = hs[k][b], h1 = hs[k + 1][b], h2 = hs[k + 2][b], h3 = hs[k + 3][b];
                acc0 += h0 * w0.x + h1 * w0.y + h2 * w0.z + h3 * w0.w;
                acc1 += h0 * w1.x + h1 * w1.y + h2 * w1.z + h3 * w1.w;
            }
            __syncthreads();
        }
        g_q[b * HH + j0 + jl]     = acc0;
        g_q[b * HH + j0 + 4 + jl] = acc1;
    }

    grid_barrier(2, 127, tid);

    {
        float* qs  = pool;
        float* was = pool + 512;
        float* ss  = pool + 1024;
        float* wgt = pool + 1088;
        int b = cta >> 1, half = cta & 1;
        int lane = tid & 31, warp = tid >> 5;

        if (half == 0) {
            int tok = __ldcg(&g_tok[b]);
            for (int i = tid; i < EE; i += 256)
                g_rnnin[b * RNNIN + i] = dec_emb[(size_t)tok * EE + i];
        }
        for (int i = tid; i < HH; i += 256) {
            qs[i] = __ldcg(&g_q[b * HH + i]);
            was[i] = W_a2[i];
        }
        __syncthreads();

        for (int tt = 0; tt < 8; tt++) {
            int t = warp * 8 + tt;
            const float* Prow = g_P + (size_t)(t * BB + b) * HH;
            float p = 0.f;
#pragma unroll 4
            for (int jj = lane; jj < HH; jj += 32)
                p += was[jj] * tanhf(qs[jj] + __ldcs(&Prow[jj]));
#pragma unroll
            for (int o = 16; o > 0; o >>= 1)
                p += __shfl_down_sync(0xffffffffu, p, o);
            if (lane == 0) ss[t] = p + b_a2[0];
        }
        __syncthreads();

        if (tid < 32) {
            float v0 = ss[tid], v1 = ss[tid + 32];
            float m = fmaxf(v0, v1);
#pragma unroll
            for (int o = 16; o > 0; o >>= 1)
                m = fmaxf(m, __shfl_xor_sync(0xffffffffu, m, o));
            float e0 = expf(v0 - m), e1 = expf(v1 - m);
            float s2 = e0 + e1;
#pragma unroll
            for (int o = 16; o > 0; o >>= 1)
                s2 += __shfl_xor_sync(0xffffffffu, s2, o);
            wgt[tid] = e0 / s2;
            wgt[tid + 32] = e1 / s2;
        }
        __syncthreads();

        int i0 = half * 512;
        for (int ii = tid; ii < 512; ii += 256) {
            int i = i0 + ii;
            float c = 0.f;
#pragma unroll 8
            for (int t = 0; t < TX; t++)
                c += wgt[t] * __ldcs(&g_enc[(size_t)(t * BB + b) * CTXD + i]);
            g_rnnin[b * RNNIN + EE + i] = c;
            g_lin[b * H3 + HH + i] = c;
            g_ah[b * H3 + HH + i] = __float2half_rn(c);
        }
    }

    grid_barrier(2, 127, tid);

    {
        float (*xs)[65] = (float(*)[65])pool;
        float* ws = pool + 128 * 65;
        int b = tid & 63;
        int jl = tid >> 6;
        int j0 = cta * 4;
        int j = j0 + jl;
        int par = s & 1;
        const float* hin = g_hd[par];
        float* hout = g_hd[par ^ 1];

        float ar = 0.f, az = 0.f, anx = 0.f, anh = 0.f;

        for (int kb = 0; kb < 10; kb++) {
            int kbase = kb * 128;
#pragma unroll
            for (int r = 0; r < 32; r++) {
                int i = tid + r * 256;
                int kk = i & 127, bb2 = i >> 7;
                xs[kk][bb2] = __ldcg(&g_rnnin[bb2 * RNNIN + kbase + kk]);
            }
#pragma unroll
            for (int r = 0; r < 6; r++) {
                int i = tid + r * 256;
                int kk = i & 127, rr = i >> 7;
                int g = rr >> 2, jloc = rr & 3;
                ws[rr * 128 + kk] = Wih[(size_t)(g * HH + j0 + jloc) * RNNIN + kbase + kk];
            }
            __syncthreads();
#pragma unroll 8
            for (int k = 0; k < 128; k += 4) {
                float4 wr = *(const float4*)&ws[jl * 128 + k];
                float4 wz = *(const float4*)&ws[(4 + jl) * 128 + k];
                float4 wn = *(const float4*)&ws[(8 + jl) * 128 + k];
                float x0 = xs[k][b], x1 = xs[k + 1][b], x2 = xs[k + 2][b], x3 = xs[k + 3][b];
                ar += x0 * wr.x + x1 * wr.y + x2 * wr.z + x3 * wr.w;
                az += x0 * wz.x + x1 * wz.y + x2 * wz.z + x3 * wz.w;
                anx += x0 * wn.x + x1 * wn.y + x2 * wn.z + x3 * wn.w;
            }
            __syncthreads();
        }

        for (int kb = 0; kb < 4; kb++) {
            int kbase = kb * 128;
#pragma unroll
            for (int r = 0; r < 32; r++) {
                int i = tid + r * 256;
                int kk = i & 127, bb2 = i >> 7;
                xs[kk][bb2] = hin[bb2 * HH + kbase + kk];
            }
#pragma unroll
            for (int r = 0; r < 6; r++) {
                int i = tid + r * 256;
                int kk = i & 127, rr = i >> 7;
                int g = rr >> 2, jloc = rr & 3;
                ws[rr * 128 + kk] = Whh[(size_t)(g * HH + j0 + jloc) * HH + kbase + kk];
            }
            __syncthreads();
#pragma unroll 8
            for (int k = 0; k < 128; k += 4) {
                float4 wr = *(const float4*)&ws[jl * 128 + k];
                float4 wz = *(const float4*)&ws[(4 + jl) * 128 + k];
                float4 wn = *(const float4*)&ws[(8 + jl) * 128 + k];
                float x0 = xs[k][b], x1 = xs[k + 1][b], x2 = xs[k + 2][b], x3 = xs[k + 3][b];
                ar += x0 * wr.x + x1 * wr.y + x2 * wr.z + x3 * wr.w;
                az += x0 * wz.x + x1 * wz.y + x2 * wz.z + x3 * wz.w;
                anh += x0 * wn.x + x1 * wn.y + x2 * wn.z + x3 * wn.w;
            }
            __syncthreads();
        }

        float r = sigm(ar + bih[j] + bhh[j]);
        float z = sigm(az + bih[HH + j] + bhh[HH + j]);
        float n = tanhf(anx + bih[2 * HH + j] + r * (anh + bhh[2 * HH + j]));
        float hold = hin[b * HH + j];
        float h2 = (1.f - z) * n + z * hold;
        hout[b * HH + j] = h2;
        g_lin[b * H3 + j] = h2;
        g_ah[b * H3 + j] = __float2half_rn(h2);
    }
}

// ---------------- generic SGEMM (clock canary: ~158us at normal clocks) ----------------
__global__ __launch_bounds__(256) void sgemm_kernel(
    const float* __restrict__ A, const int* __restrict__ gather,
    const float* __restrict__ W, int ldw,
    const float* __restrict__ bias,
    float* __restrict__ C, int N, int K)
{
    __shared__ float As[16][64];
    __shared__ float Ws[16][128];
    int tid = threadIdx.x;
    int m0 = blockIdx.y * 64;
    int n0 = blockIdx.x * 128;
    int tx = tid & 15, ty = tid >> 4;

    float acc[4][8];
#pragma unroll
    for (int i = 0; i < 4; i++)
#pragma unroll
        for (int j = 0; j < 8; j++) acc[i][j] = 0.f;

    int lrow = tid >> 2;
    int lk = (tid & 3) * 4;
    int arow = m0 + lrow;
    int aphys = gather ? gather[arow] : arow;
    const float* Aptr = A + (size_t)aphys * K + lk;

    for (int k0 = 0; k0 < K; k0 += 16) {
        float4 av = *(const float4*)(Aptr + k0);
        As[lk + 0][lrow] = av.x; As[lk + 1][lrow] = av.y;
        As[lk + 2][lrow] = av.z; As[lk + 3][lrow] = av.w;
#pragma unroll
        for (int r = 0; r < 2; r++) {
            int nrow = lrow + r * 64;
            float4 wv = *(const float4*)(W + (size_t)(n0 + nrow) * ldw + k0 + lk);
            Ws[lk + 0][nrow] = wv.x; Ws[lk + 1][nrow] = wv.y;
            Ws[lk + 2][nrow] = wv.z; Ws[lk + 3][nrow] = wv.w;
        }
        __syncthreads();
#pragma unroll
        for (int kk = 0; kk < 16; kk++) {
            float a[4];
#pragma unroll
            for (int i = 0; i < 4; i++) a[i] = As[kk][ty * 4 + i];
            float4 b0 = *(const float4*)&Ws[kk][tx * 8];
            float4 b1 = *(const float4*)&Ws[kk][tx * 8 + 4];
            float bb8[8] = { b0.x, b0.y, b0.z, b0.w, b1.x, b1.y, b1.z, b1.w };
#pragma unroll
            for (int i = 0; i < 4; i++)
#pragma unroll
                for (int j = 0; j < 8; j++) acc[i][j] += a[i] * bb8[j];
        }
        __syncthreads();
    }
#pragma unroll
    for (int i = 0; i < 4; i++) {
        int m = m0 + ty * 4 + i;
        float* crow = C + (size_t)m * N + n0 + tx * 8;
#pragma unroll
        for (int j = 0; j < 8; j++) {
            float v = acc[i][j];
            if (bias) v += bias[n0 + tx * 8 + j];
            crow[j] = v;
        }
    }
}

// ---------------- persistent encoder ----------------
#define ENC_WS_FLOATS (24 * 512)
#define ENC_SMEM ((ENC_WS_FLOATS + 128 * 65) * 4)

__global__ __launch_bounds__(512, 1) void enc_persist_kernel(
    const float* __restrict__ Whh_f, const float* __restrict__ bhh_f,
    const float* __restrict__ Whh_b, const float* __restrict__ bhh_b)
{
    extern __shared__ float smf_[];
    float* ws = smf_;
    float (*hs)[65] = (float(*)[65])(smf_ + ENC_WS_FLOATS);

    int dir = blockIdx.y;
    const float* Whh = dir ? Whh_b : Whh_f;
    const float* bhh = dir ? bhh_b : bhh_f;
    int tid = threadIdx.x;
    int b = tid & 63;
    int jl = tid >> 6;
    int j0 = blockIdx.x * 8;
    int j = j0 + jl;
    int colofs = dir ? HH : 0;

    for (int idx = tid; idx < ENC_WS_FLOATS; idx += 512) {
        int rr = idx >> 9, kk = idx & 511;
        ws[idx] = Whh[(size_t)((rr >> 3) * HH + j0 + (rr & 7)) * HH + kk];
    }
    float br = bhh[j], bz = bhh[HH + j], bn = bhh[2 * HH + j];
    __syncthreads();

    for (int t = 0; t < TX; t++) {
        int par = t & 1;
        int row = dir ? (TX - 1 - t) : t;
        const float* gi = (dir ? g_gi_b : g_gi_f) + (size_t)row * BB * H3;
        const float* hin = g_henc[dir][par];
        float* hout = g_henc[dir][par ^ 1];

        float dr = 0.f, dz = 0.f, dn = 0.f;
        for (int kb = 0; kb < 4; kb++) {
            int kbase = kb * 128;
#pragma unroll
            for (int r = 0; r < 16; r++) {
                int i = tid + r * 512;
                int kk = i & 127, bb2 = i >> 7;
                hs[kk][bb2] = __ldcg(&hin[bb2 * HH + kbase + kk]);
            }
            __syncthreads();
            const float* wr4 = ws + jl * 512 + kbase;
            const float* wz4 = ws + (8 + jl) * 512 + kbase;
            const float* wn4 = ws + (16 + jl) * 512 + kbase;
#pragma unroll 8
            for (int k = 0; k < 128; k += 4) {
                float4 wr = *(const float4*)(wr4 + k);
                float4 wz = *(const float4*)(wz4 + k);
                float4 wn = *(const float4*)(wn4 + k);
                float h0 = hs[k][b], h1 = hs[k + 1][b], h2v = hs[k + 2][b], h3v = hs[k + 3][b];
                dr += h0 * wr.x + h1 * wr.y + h2v * wr.z + h3v * wr.w;
                dz += h0 * wz.x + h1 * wz.y + h2v * wz.z + h3v * wz.w;
                dn += h0 * wn.x + h1 * wn.y + h2v * wn.z + h3v * wn.w;
            }
            __syncthreads();
        }

        const float* girow = gi + b * H3;
        float r = sigm(girow[j] + dr + br);
        float z = sigm(girow[HH + j] + dz + bz);
        float n = tanhf(girow[2 * HH + j] + r * (dn + bn));
        float hold = __ldcg(&hin[b * HH + j]);
        float h2 = (1.f - z) * n + z * hold;
        __stcg(&hout[b * HH + j], h2);
        g_enc[(size_t)(row * BB + b) * CTXD + colofs + j] = h2;

        if (t + 1 < TX) grid_barrier(dir, 63, tid);
    }
}

// ---------------- column projection (hidden init only) ----------------
__global__ __launch_bounds__(512) void colproj_kernel(
    const float* __restrict__ src, const float* __restrict__ W, int ldw,
    const float* __restrict__ bias, float* __restrict__ dst, int act)
{
    __shared__ float hs[128][65];
    __shared__ float ws[8][128];
    int tid = threadIdx.x;
    int b = tid & 63;
    int jl = tid >> 6;
    int j0 = blockIdx.x * 8;
    int j = j0 + jl;

    float acc = 0.f;
    for (int kb = 0; kb < 4; kb++) {
        int kbase = kb * 128;
#pragma unroll
        for (int r = 0; r < 16; r++) {
            int i = tid + r * 512;
            int kk = i & 127, bb2 = i >> 7;
            hs[kk][bb2] = src[bb2 * HH + kbase + kk];
        }
#pragma unroll
        for (int r = 0; r < 2; r++) {
            int i = tid + r * 512;
            int kk = i & 127, rr = i >> 7;
            ws[rr][kk] = W[(size_t)(j0 + rr) * ldw + kbase + kk];
        }
        __syncthreads();
#pragma unroll 8
        for (int k = 0; k < 128; k += 4) {
            float4 wv = *(const float4*)&ws[jl][k];
            acc += hs[k][b] * wv.x + hs[k + 1][b] * wv.y
                 + hs[k + 2][b] * wv.z + hs[k + 3][b] * wv.w;
        }
        __syncthreads();
    }
    if (bias) acc += bias[j];
    if (act) acc = tanhf(acc);
    dst[b * HH + j] = acc;
}

// ---------------- host launch ----------------
extern "C" void kernel_launch(void* const* d_in, const int* in_sizes, int n_in,
                              void* d_out, int out_size)
{
    const int*   inputs  = (const int*)d_in[0];
    const float* enc_emb = (const float*)d_in[2];
    const float* W_ih_f  = (const float*)d_in[3];
    const float* W_hh_f  = (const float*)d_in[4];
    const float* b_ih_f  = (const float*)d_in[5];
    const float* b_hh_f  = (const float*)d_in[6];
    const float* W_ih_b  = (const float*)d_in[7];
    const float* W_hh_b  = (const float*)d_in[8];
    const float* b_ih_b  = (const float*)d_in[9];
    const float* b_hh_b  = (const float*)d_in[10];
    const float* W_init  = (const float*)d_in[11];
    const float* b_init  = (const float*)d_in[12];
    const float* dec_emb = (const float*)d_in[13];
    const float* W_ih_d  = (const float*)d_in[14];
    const float* W_hh_d  = (const float*)d_in[15];
    const float* b_ih_d  = (const float*)d_in[16];
    const float* b_hh_d  = (const float*)d_in[17];
    const float* W_lsm   = (const float*)d_in[18];
    const float* b_lsm   = (const float*)d_in[19];
    const float* W_a1    = (const float*)d_in[20];
    const float* b_a1    = (const float*)d_in[21];
    const float* W_a2    = (const float*)d_in[22];
    const float* b_a2    = (const float*)d_in[23];
    float* out = (float*)d_out;

    static float* p_P    = nullptr;
    static float* p_gi_f = nullptr;
    static float* p_gi_b = nullptr;
    static float* p_enc  = nullptr;
    static float* p_hd   = nullptr;
    static float* p_henc = nullptr;
    static cudaStream_t s2 = nullptr;
    static cudaEvent_t ev_root, ev_w;
    if (!p_gi_f) {
        cudaGetSymbolAddress((void**)&p_gi_f, g_gi_f);
        cudaGetSymbolAddress((void**)&p_gi_b, g_gi_b);
        cudaGetSymbolAddress((void**)&p_enc,  g_enc);
        cudaGetSymbolAddress((void**)&p_P,    g_P);
        cudaGetSymbolAddress((void**)&p_hd,   g_hd);
        cudaGetSymbolAddress((void**)&p_henc, g_henc);
        cudaFuncSetAttribute(logits_mma_kernel,
                             cudaFuncAttributeMaxDynamicSharedMemorySize, LG_SMEM_TOTAL);
        cudaFuncSetAttribute(enc_persist_kernel,
                             cudaFuncAttributeMaxDynamicSharedMemorySize, ENC_SMEM);
        cudaStreamCreateWithFlags(&s2, cudaStreamNonBlocking);
        cudaEventCreateWithFlags(&ev_root, cudaEventDisableTiming);
        cudaEventCreateWithFlags(&ev_w,    cudaEventDisableTiming);
    }

    cudaEventRecord(ev_root, 0);

    init_kernel<<<128, 256>>>();

    sgemm_kernel<<<dim3(H3 / 128, TX * BB / 64), 256>>>(
        enc_emb, inputs, W_ih_f, EE, b_ih_f, p_gi_f, H3, EE);
    sgemm_kernel<<<dim3(H3 / 128, TX * BB / 64), 256>>>(
        enc_emb, inputs, W_ih_b, EE, b_ih_b, p_gi_b, H3, EE);

    enc_persist_kernel<<<dim3(64, 2), 512, ENC_SMEM>>>(
        W_hh_f, b_hh_f, W_hh_b, b_hh_b);

    // convw on stream 2 (executes from t=0 via ev_root)
    cudaStreamWaitEvent(s2, ev_root, 0);
    convw_kernel<<<(int)(((size_t)KY * H3 / 4) / 256), 256, 0, s2>>>(W_lsm);
    cudaEventRecord(ev_w, s2);

    sgemm_kernel<<<dim3(HH / 128, TX * BB / 64), 256>>>(
        p_enc, nullptr, W_a1 + HH, H3, b_a1, p_P, HH, CTXD);

    colproj_kernel<<<64, 512>>>(p_henc + 2 * BB * HH, W_init, HH, b_init, p_hd, 1);

    cudaStreamWaitEvent(0, ev_w, 0);

    for (int s = 0; s < TY; s++) {
        step_kernel<<<128, 256>>>(s, W_lsm, b_lsm, W_a1, W_a2, b_a2, dec_emb,
                                  W_ih_d, W_hh_d, b_ih_d, b_hh_d);
        logits_mma_kernel<<<NTILE, 256, LG_SMEM_TOTAL>>>(b_lsm, out, s);
    }

    // final step's lse then normalize everything (streaming)
    lsm_argmax_kernel<<<64, 256>>>(W_lsm, b_lsm, TY - 1);
    lsm_norm_all_kernel<<<(int)((size_t)TY * BB * KY / 4 / 256), 256>>>(out);
}